// round 16
// baseline (speedup 1.0000x reference)
#include <cuda_runtime.h>
#include <cuda_bf16.h>
#include <cstdint>

// OverlapPatchEmbed: x (B=64, C=3, H=224, W=224) f32 -> out (B, 729, C, 256) f32
// out[b][pi*27+pj][c][r*16+s] = x[b][c][pi*8+r][pj*8+s]
//
// 9-band groups (block = (b, c, grp), 80 contiguous rows loaded once via one
// TMA bulk copy; read amplification 1.07x). TPB=1024, 2 CTAs/SM:
// 2048 resident threads and 576/296 = 1.95 -> two nearly-full waves
// (vs 3-CTA/512-thread: 1.3 ragged waves with a 30%-fill tail).
// Store: 9 bands, conflict-free LDS.128 (natural pitch 56) + coalesced
// streaming STG.128 (__stcs).

namespace {
constexpr int B  = 64;
constexpr int C  = 3;
constexpr int H  = 224;
constexpr int W  = 224;      // 56 float4 per row
constexpr int N  = 27;
constexpr int NG = 3;        // groups per (b,c), 9 bands each
constexpr int BANDS = 9;
constexpr int TPB = 1024;

constexpr int W4      = W / 4;              // 56 = natural smem pitch
constexpr int GROWS   = BANDS * 8 + 8;      // 80 rows per group
constexpr int LOAD_BYTES = GROWS * W4 * 16; // 71680
constexpr int STORE_V = N * 64;             // 1728 float4 per band
constexpr int NBLOCKS = B * C * NG;         // 576
constexpr int SK = 2;                       // ceil(1728/1024)
}

__global__ __launch_bounds__(TPB, 2)
void overlap_patch_kernel(const float4* __restrict__ x, float4* __restrict__ out)
{
    extern __shared__ float4 s[];                    // 71680 bytes dynamic
    __shared__ alignas(8) unsigned long long mbar;

    const int bx  = blockIdx.x;
    const int grp = bx % NG;
    const int c   = (bx / NG) % C;
    const int b   = bx / (NG * C);
    const int tid = threadIdx.x;
    const int pi0 = grp * BANDS;

    uint32_t s_addr, mbar_addr;
    asm("{ .reg .u64 t; cvta.to.shared.u64 t, %1; cvt.u32.u64 %0, t; }"
        : "=r"(s_addr) : "l"((void*)s));
    asm("{ .reg .u64 t; cvta.to.shared.u64 t, %1; cvt.u32.u64 %0, t; }"
        : "=r"(mbar_addr) : "l"((void*)&mbar));

    if (tid == 0) {
        asm volatile("mbarrier.init.shared.b64 [%0], 1;" :: "r"(mbar_addr) : "memory");
    }
    __syncthreads();

    if (tid == 0) {
        asm volatile("mbarrier.arrive.expect_tx.shared.b64 _, [%0], %1;"
                     :: "r"(mbar_addr), "r"((uint32_t)LOAD_BYTES) : "memory");
        const int in_base = ((b * C + c) * H + pi0 * 8) * W4;   // float4 index
        asm volatile(
            "cp.async.bulk.shared::cta.global.mbarrier::complete_tx::bytes "
            "[%0], [%1], %2, [%3];"
            :: "r"(s_addr), "l"(x + in_base), "r"((uint32_t)LOAD_BYTES),
               "r"(mbar_addr) : "memory");
    }

    // wait for bulk load (acquire orders smem reads after TMA writes)
    {
        uint32_t done;
        asm volatile(
            "{\n\t"
            ".reg .pred p;\n\t"
            "mbarrier.try_wait.parity.acquire.cta.shared::cta.b64 p, [%1], 0;\n\t"
            "selp.b32 %0, 1, 0, p;\n\t"
            "}"
            : "=r"(done) : "r"(mbar_addr) : "memory");
        if (!done) {
            asm volatile(
                "{\n\t"
                ".reg .pred P1;\n\t"
                "WAIT_LOOP:\n\t"
                "mbarrier.try_wait.parity.acquire.cta.shared::cta.b64 P1, [%0], 0, 0x989680;\n\t"
                "@P1 bra.uni WAIT_DONE;\n\t"
                "bra.uni WAIT_LOOP;\n\t"
                "WAIT_DONE:\n\t"
                "}"
                :: "r"(mbar_addr) : "memory");
        }
    }
    __syncthreads();

    // ---- store phase: 9 bands, fully coalesced streaming STG.128 ----
    #pragma unroll
    for (int sub = 0; sub < BANDS; sub++) {
        const int pi  = pi0 + sub;
        const int ob0 = ((b * (N * N) + pi * N) * C + c) * 64;
        const int srow0 = sub * 8;

        float4 sv[SK];
        #pragma unroll
        for (int k = 0; k < SK; k++) {
            int j = tid + k * TPB;
            if (j < STORE_V) {
                int pj = j >> 6;
                int q  = j & 63;
                int r  = q >> 2;
                int s4 = q & 3;
                sv[k] = s[(srow0 + r) * W4 + pj * 2 + s4];
            }
        }
        #pragma unroll
        for (int k = 0; k < SK; k++) {
            int j = tid + k * TPB;
            if (j < STORE_V) {
                int pj = j >> 6;
                int q  = j & 63;
                __stcs(&out[ob0 + pj * (C * 64) + q], sv[k]);
            }
        }
    }
}

extern "C" void kernel_launch(void* const* d_in, const int* in_sizes, int n_in,
                              void* d_out, int out_size)
{
    const float4* x = (const float4*)d_in[0];
    float4* out = (float4*)d_out;

    static bool configured = false;
    if (!configured) {
        cudaFuncSetAttribute(overlap_patch_kernel,
                             cudaFuncAttributeMaxDynamicSharedMemorySize,
                             LOAD_BYTES);
        configured = true;
    }
    overlap_patch_kernel<<<NBLOCKS, TPB, LOAD_BYTES>>>(x, out);
}

// round 17
// speedup vs baseline: 1.0032x; 1.0032x over previous
#include <cuda_runtime.h>
#include <cuda_bf16.h>
#include <cstdint>

// OverlapPatchEmbed: x (B=64, C=3, H=224, W=224) f32 -> out (B, 729, C, 256) f32
// out[b][pi*27+pj][c][r*16+s] = x[b][c][pi*8+r][pj*8+s]
//
// 9-band groups (block = (b, c, grp), 80 contiguous rows), TPB=512, 3 CTAs/SM.
// STAGED TMA drain: three cp.async.bulk chunks (rows 0-31 / 32-63 / 64-79),
// each with its own mbarrier. Stores of bands 0-2 start as soon as chunk 0
// lands; bands 3-6 after chunk 1; bands 7-8 after chunk 2. TMA fills produce
// no L1tex wavefronts, so the overlapped stores don't contend with fills.
// Per-thread mbarrier waits replace __syncthreads in the drain.

namespace {
constexpr int B  = 64;
constexpr int C  = 3;
constexpr int H  = 224;
constexpr int W  = 224;      // 56 float4 per row
constexpr int N  = 27;
constexpr int NG = 3;        // groups per (b,c), 9 bands each
constexpr int BANDS = 9;
constexpr int TPB = 512;

constexpr int W4      = W / 4;              // 56 = natural smem pitch
constexpr int GROWS   = BANDS * 8 + 8;      // 80 rows per group
constexpr int LOAD_BYTES = GROWS * W4 * 16; // 71680
constexpr int STORE_V = N * 64;             // 1728 float4 per band
constexpr int NBLOCKS = B * C * NG;         // 576
constexpr int SK = 4;                       // ceil(1728/512)

// stage row extents
constexpr int S0_ROWS = 32;                 // bands 0-2 covered (rows 0-31)
constexpr int S1_ROWS = 32;                 // rows 32-63 -> bands 3-6
constexpr int S2_ROWS = 16;                 // rows 64-79 -> bands 7-8
constexpr int S0_BYTES = S0_ROWS * W4 * 16; // 28672
constexpr int S1_BYTES = S1_ROWS * W4 * 16; // 28672
constexpr int S2_BYTES = S2_ROWS * W4 * 16; // 14336
}

__device__ __forceinline__ void mbar_wait(uint32_t addr)
{
    uint32_t done;
    asm volatile(
        "{\n\t"
        ".reg .pred p;\n\t"
        "mbarrier.try_wait.parity.acquire.cta.shared::cta.b64 p, [%1], 0;\n\t"
        "selp.b32 %0, 1, 0, p;\n\t"
        "}"
        : "=r"(done) : "r"(addr) : "memory");
    if (!done) {
        asm volatile(
            "{\n\t"
            ".reg .pred P1;\n\t"
            "WAIT_LOOP_%=:\n\t"
            "mbarrier.try_wait.parity.acquire.cta.shared::cta.b64 P1, [%0], 0, 0x989680;\n\t"
            "@P1 bra.uni WAIT_DONE_%=;\n\t"
            "bra.uni WAIT_LOOP_%=;\n\t"
            "WAIT_DONE_%=:\n\t"
            "}"
            :: "r"(addr) : "memory");
    }
}

__global__ __launch_bounds__(TPB, 3)
void overlap_patch_kernel(const float4* __restrict__ x, float4* __restrict__ out)
{
    extern __shared__ float4 s[];                    // 71680 bytes dynamic
    __shared__ alignas(8) unsigned long long mbar[3];

    const int bx  = blockIdx.x;
    const int grp = bx % NG;
    const int c   = (bx / NG) % C;
    const int b   = bx / (NG * C);
    const int tid = threadIdx.x;
    const int pi0 = grp * BANDS;

    uint32_t s_addr, m_addr;
    asm("{ .reg .u64 t; cvta.to.shared.u64 t, %1; cvt.u32.u64 %0, t; }"
        : "=r"(s_addr) : "l"((void*)s));
    asm("{ .reg .u64 t; cvta.to.shared.u64 t, %1; cvt.u32.u64 %0, t; }"
        : "=r"(m_addr) : "l"((void*)mbar));

    if (tid == 0) {
        asm volatile("mbarrier.init.shared.b64 [%0], 1;" :: "r"(m_addr)      : "memory");
        asm volatile("mbarrier.init.shared.b64 [%0], 1;" :: "r"(m_addr + 8)  : "memory");
        asm volatile("mbarrier.init.shared.b64 [%0], 1;" :: "r"(m_addr + 16) : "memory");
    }
    __syncthreads();

    if (tid == 0) {
        const int in_base = ((b * C + c) * H + pi0 * 8) * W4;   // float4 index
        // stage 0: rows 0-31
        asm volatile("mbarrier.arrive.expect_tx.shared.b64 _, [%0], %1;"
                     :: "r"(m_addr), "r"((uint32_t)S0_BYTES) : "memory");
        asm volatile(
            "cp.async.bulk.shared::cta.global.mbarrier::complete_tx::bytes "
            "[%0], [%1], %2, [%3];"
            :: "r"(s_addr), "l"(x + in_base), "r"((uint32_t)S0_BYTES),
               "r"(m_addr) : "memory");
        // stage 1: rows 32-63
        asm volatile("mbarrier.arrive.expect_tx.shared.b64 _, [%0], %1;"
                     :: "r"(m_addr + 8), "r"((uint32_t)S1_BYTES) : "memory");
        asm volatile(
            "cp.async.bulk.shared::cta.global.mbarrier::complete_tx::bytes "
            "[%0], [%1], %2, [%3];"
            :: "r"(s_addr + S0_BYTES), "l"(x + in_base + S0_ROWS * W4),
               "r"((uint32_t)S1_BYTES), "r"(m_addr + 8) : "memory");
        // stage 2: rows 64-79
        asm volatile("mbarrier.arrive.expect_tx.shared.b64 _, [%0], %1;"
                     :: "r"(m_addr + 16), "r"((uint32_t)S2_BYTES) : "memory");
        asm volatile(
            "cp.async.bulk.shared::cta.global.mbarrier::complete_tx::bytes "
            "[%0], [%1], %2, [%3];"
            :: "r"(s_addr + S0_BYTES + S1_BYTES),
               "l"(x + in_base + (S0_ROWS + S1_ROWS) * W4),
               "r"((uint32_t)S2_BYTES), "r"(m_addr + 16) : "memory");
    }

    // ---- staged drain + store: band sub needs rows 8*sub .. 8*sub+15 ----
    #pragma unroll
    for (int sub = 0; sub < BANDS; sub++) {
        if (sub == 0) mbar_wait(m_addr);            // rows 0-31 ready
        if (sub == 3) mbar_wait(m_addr + 8);        // rows 32-63 ready
        if (sub == 7) mbar_wait(m_addr + 16);       // rows 64-79 ready

        const int pi  = pi0 + sub;
        const int ob0 = ((b * (N * N) + pi * N) * C + c) * 64;
        const int srow0 = sub * 8;

        float4 sv[SK];
        #pragma unroll
        for (int k = 0; k < SK; k++) {
            int j = tid + k * TPB;
            if (j < STORE_V) {
                int pj = j >> 6;
                int q  = j & 63;
                int r  = q >> 2;
                int s4 = q & 3;
                sv[k] = s[(srow0 + r) * W4 + pj * 2 + s4];
            }
        }
        #pragma unroll
        for (int k = 0; k < SK; k++) {
            int j = tid + k * TPB;
            if (j < STORE_V) {
                int pj = j >> 6;
                int q  = j & 63;
                __stcs(&out[ob0 + pj * (C * 64) + q], sv[k]);
            }
        }
    }
}

extern "C" void kernel_launch(void* const* d_in, const int* in_sizes, int n_in,
                              void* d_out, int out_size)
{
    const float4* x = (const float4*)d_in[0];
    float4* out = (float4*)d_out;

    static bool configured = false;
    if (!configured) {
        cudaFuncSetAttribute(overlap_patch_kernel,
                             cudaFuncAttributeMaxDynamicSharedMemorySize,
                             LOAD_BYTES);
        configured = true;
    }
    overlap_patch_kernel<<<NBLOCKS, TPB, LOAD_BYTES>>>(x, out);
}